// round 5
// baseline (speedup 1.0000x reference)
#include <cuda_runtime.h>
#include <cuda_fp16.h>

// BSplineACTF: per-channel cubic B-spline activation, uniform knots.
// x:[16,256,256,32] f32, grid:[12] f32, W:[32,8] f32 -> out f32.
//
// R4 post-mortem: unroll-4 + .cs hints regressed (regs pinned at 32, chains
// re-interleaved, MLP never materialized). R5: revert to R3 schedule, then
//  (a) single-wave persistent grid (148 SMs x 4 blocks, zero wave transitions)
//  (b) depth-2 software prefetch: LDG for iter i+2 issued before compute/store
//      of iter i -> 2 loads always in flight at only +8 regs.
// Table: fp16-packed collapsed cubic per (channel, interval), one LDS.64.

#define NTHREADS 256
#define NBLOCKS  592   // 148 SMs x 4 blocks x 8 warps = full single wave

__global__ __launch_bounds__(NTHREADS) void bspline_actf_kernel(
    const float* __restrict__ x,
    const float* __restrict__ grid,
    const float* __restrict__ W,
    float* __restrict__ out,
    int n)
{
    // [channel][interval] packed cubic coeffs: lo=(c0,c1), hi=(c2,c3) as half2.
    __shared__ uint2 sc[32 * 11];

    const float g0    = grid[0];
    const float g11   = grid[11];
    const float h     = (g11 - g0) * (1.0f / 11.0f);
    const float inv_h = 1.0f / h;

    // ---- one-time per-block coefficient build (352 records) ----
    for (int idx = threadIdx.x; idx < 32 * 11; idx += NTHREADS) {
        int c = idx / 11;
        int j = idx - c * 11;
        const float* Wc = W + c * 8;
        float w0 = (j     >= 0 && j     < 8) ? __ldg(Wc + j)     : 0.0f;
        float w1 = (j - 1 >= 0 && j - 1 < 8) ? __ldg(Wc + j - 1) : 0.0f;
        float w2 = (j - 2 >= 0 && j - 2 < 8) ? __ldg(Wc + j - 2) : 0.0f;
        float w3 = (j - 3 >= 0 && j - 3 < 8) ? __ldg(Wc + j - 3) : 0.0f;
        float c0 = (w1 + 4.0f * w2 + w3) * (1.0f / 6.0f);
        float c1 = (w1 - w3) * 0.5f;
        float c2 = (w1 - 2.0f * w2 + w3) * 0.5f;
        float c3 = (w0 - 3.0f * w1 + 3.0f * w2 - w3) * (1.0f / 6.0f);
        __half2 lo = __floats2half2_rn(c0, c1);
        __half2 hi = __floats2half2_rn(c2, c3);
        uint2 rec;
        rec.x = *reinterpret_cast<unsigned int*>(&lo);
        rec.y = *reinterpret_cast<unsigned int*>(&hi);
        sc[idx] = rec;
    }
    __syncthreads();

    const int gtid   = blockIdx.x * NTHREADS + threadIdx.x;
    const int stride = gridDim.x * NTHREADS;   // in float4 vectors; % 8 == 0
    const int n4     = n >> 2;

    // channel quartet of this thread's vectors is loop-invariant
    const int c0i = (gtid & 7) * 4;
    const uint2* __restrict__ row0 = sc + (c0i + 0) * 11;
    const uint2* __restrict__ row1 = sc + (c0i + 1) * 11;
    const uint2* __restrict__ row2 = sc + (c0i + 2) * 11;
    const uint2* __restrict__ row3 = sc + (c0i + 3) * 11;

    const float4* __restrict__ x4 = (const float4*)x;
    float4* __restrict__ o4       = (float4*)out;

    auto evalspline = [&](float xv, const uint2* __restrict__ rowp) -> float {
        float u  = (xv - g0) * inv_h;
        float jf = floorf(u);
        int   j  = (int)jf;
        float t  = u - jf;
        int   jc = min(max(j, 0), 10);
        uint2 rec = rowp[jc];                 // LDS.64
        __half2 lo = *reinterpret_cast<__half2*>(&rec.x);
        __half2 hi = *reinterpret_cast<__half2*>(&rec.y);
        float2 f01 = __half22float2(lo);
        float2 f23 = __half22float2(hi);
        float r = fmaf(fmaf(fmaf(f23.y, t, f23.x), t, f01.y), t, f01.x);
        return ((unsigned)j < 11u) ? r : 0.0f;
    };

    auto eval_vec = [&](float4 xv) -> float4 {
        float4 ov;
        ov.x = evalspline(xv.x, row0);
        ov.y = evalspline(xv.y, row1);
        ov.z = evalspline(xv.z, row2);
        ov.w = evalspline(xv.w, row3);
        return ov;
    };

    // ---- depth-2 software-pipelined grid-stride loop ----
    int v = gtid;
    if (v < n4) {
        int v1 = v + stride;
        float4 xa = x4[v];
        float4 xb = x4[(v1 < n4) ? v1 : v];      // clamped prefetch (dup ok)
        while (v < n4) {
            int v2 = v1 + stride;
            float4 xc = x4[(v2 < n4) ? v2 : v];  // prefetch i+2
            o4[v] = eval_vec(xa);                // compute+store i
            xa = xb; xb = xc;
            v = v1; v1 = v2;
        }
    }

    // scalar tail (n % 4) — not hit for this shape, kept for safety
    for (int e = (n4 << 2) + gtid; e < n; e += stride) {
        int c = e & 31;
        out[e] = evalspline(x[e], sc + c * 11);
    }
}

extern "C" void kernel_launch(void* const* d_in, const int* in_sizes, int n_in,
                              void* d_out, int out_size)
{
    const float* x    = (const float*)d_in[0];
    const float* grid = (const float*)d_in[1];
    const float* W    = (const float*)d_in[2];
    float* out        = (float*)d_out;
    int n = in_sizes[0];

    int n4 = n >> 2;
    int blocks = NBLOCKS;
    int maxBlocks = (n4 + NTHREADS - 1) / NTHREADS;
    if (maxBlocks < 1) maxBlocks = 1;
    if (blocks > maxBlocks) blocks = maxBlocks;

    bspline_actf_kernel<<<blocks, NTHREADS>>>(x, grid, W, out, n);
}

// round 6
// speedup vs baseline: 1.0375x; 1.0375x over previous
#include <cuda_runtime.h>
#include <cuda_fp16.h>

// BSplineACTF: per-channel cubic B-spline activation, uniform knots.
// x:[16,256,256,32] f32, grid:[12] f32, W:[32,8] f32 -> out f32.
//
// R6: converter-pipe (XU) relief. floorf+F2I replaced by a bit-trick floor
// (FADD + integer ops, zero conversions); range check folded into a 13-row
// table with zero rows at j=-1 and j=11. Remaining XU: 2x H2F coeff unpack.
// Loop: R3's 2-way unroll, 2368 blocks (best measured schedule).

#define NTHREADS 256
#define NBLOCKS  2368

#define MAGIC_F   6291456.0f        // 1.5 * 2^22, ULP = 0.5 in its binade
#define MAGIC_I   0x4AC00000        // __float_as_int(6291456.0f)

__global__ __launch_bounds__(NTHREADS) void bspline_actf_kernel(
    const float* __restrict__ x,
    const float* __restrict__ grid,
    const float* __restrict__ W,
    float* __restrict__ out,
    int n)
{
    // [channel][slot] packed cubic coeffs: lo=(c0,c1), hi=(c2,c3) as half2.
    // slot s corresponds to interval j = s-1; s=0 and s=12 are zero rows.
    __shared__ uint2 sc[32 * 13];

    const float g0    = grid[0];
    const float g11   = grid[11];
    const float h     = (g11 - g0) * (1.0f / 11.0f);
    const float inv_h = 1.0f / h;
    // us = (x - g0)*inv_h + 1 (row shift) - 0.25 (floor-trick offset)
    const float bias  = -g0 * inv_h + 0.75f;

    // ---- one-time per-block coefficient build (416 records) ----
    for (int idx = threadIdx.x; idx < 32 * 13; idx += NTHREADS) {
        int c = idx / 13;
        int s = idx - c * 13;
        int j = s - 1;
        uint2 rec = make_uint2(0u, 0u);
        if (j >= 0 && j <= 10) {
            const float* Wc = W + c * 8;
            float w0 = (j     >= 0 && j     < 8) ? __ldg(Wc + j)     : 0.0f;
            float w1 = (j - 1 >= 0 && j - 1 < 8) ? __ldg(Wc + j - 1) : 0.0f;
            float w2 = (j - 2 >= 0 && j - 2 < 8) ? __ldg(Wc + j - 2) : 0.0f;
            float w3 = (j - 3 >= 0 && j - 3 < 8) ? __ldg(Wc + j - 3) : 0.0f;
            float c0 = (w1 + 4.0f * w2 + w3) * (1.0f / 6.0f);
            float c1 = (w1 - w3) * 0.5f;
            float c2 = (w1 - 2.0f * w2 + w3) * 0.5f;
            float c3 = (w0 - 3.0f * w1 + 3.0f * w2 - w3) * (1.0f / 6.0f);
            __half2 lo = __floats2half2_rn(c0, c1);
            __half2 hi = __floats2half2_rn(c2, c3);
            rec.x = *reinterpret_cast<unsigned int*>(&lo);
            rec.y = *reinterpret_cast<unsigned int*>(&hi);
        }
        sc[idx] = rec;
    }
    __syncthreads();

    const int gtid   = blockIdx.x * NTHREADS + threadIdx.x;
    const int stride = gridDim.x * NTHREADS;   // in float4 vectors; % 8 == 0
    const int n4     = n >> 2;

    // channel quartet of this thread's vectors is loop-invariant
    const int c0i = (gtid & 7) * 4;
    const uint2* __restrict__ row0 = sc + (c0i + 0) * 13;
    const uint2* __restrict__ row1 = sc + (c0i + 1) * 13;
    const uint2* __restrict__ row2 = sc + (c0i + 2) * 13;
    const uint2* __restrict__ row3 = sc + (c0i + 3) * 13;

    const float4* __restrict__ x4 = (const float4*)x;
    float4* __restrict__ o4       = (float4*)out;

    auto evalspline = [&](float xv, const uint2* __restrict__ rowp) -> float {
        // us = floor-target - 0.25; clamp keeps slot in [0, 12]
        float us = fmaf(xv, inv_h, bias);
        us = fminf(fmaxf(us, -0.25f), 12.25f);
        float f  = us + MAGIC_F;                 // round-to-nearest-0.5 of us
        int idx2 = __float_as_int(f) - MAGIC_I;  // = 2*r', r' = rounded us
        float rp = f - MAGIC_F;                  // r' exactly
        float d  = us - rp;                      // in [-0.25, 0.25)
        int   s  = idx2 >> 1;                    // floor(us + 0.25) = slot
        float t  = d + ((idx2 & 1) ? 0.75f : 0.25f);
        uint2 rec = rowp[s];                     // LDS.64
        __half2 lo = *reinterpret_cast<__half2*>(&rec.x);
        __half2 hi = *reinterpret_cast<__half2*>(&rec.y);
        float2 f01 = __half22float2(lo);
        float2 f23 = __half22float2(hi);
        return fmaf(fmaf(fmaf(f23.y, t, f23.x), t, f01.y), t, f01.x);
    };

    auto eval_vec = [&](float4 xv) -> float4 {
        float4 ov;
        ov.x = evalspline(xv.x, row0);
        ov.y = evalspline(xv.y, row1);
        ov.z = evalspline(xv.z, row2);
        ov.w = evalspline(xv.w, row3);
        return ov;
    };

    // 2-way unrolled grid-stride loop (R3 schedule)
    int v = gtid;
    for (; v + stride < n4; v += 2 * stride) {
        float4 xa = x4[v];
        float4 xb = x4[v + stride];
        float4 oa = eval_vec(xa);
        float4 ob = eval_vec(xb);
        o4[v]          = oa;
        o4[v + stride] = ob;
    }
    if (v < n4) {
        o4[v] = eval_vec(x4[v]);
    }

    // scalar tail (n % 4) — not hit for this shape, kept for safety
    for (int e = (n4 << 2) + gtid; e < n; e += stride) {
        int c = e & 31;
        out[e] = evalspline(x[e], sc + c * 13);
    }
}

extern "C" void kernel_launch(void* const* d_in, const int* in_sizes, int n_in,
                              void* d_out, int out_size)
{
    const float* x    = (const float*)d_in[0];
    const float* grid = (const float*)d_in[1];
    const float* W    = (const float*)d_in[2];
    float* out        = (float*)d_out;
    int n = in_sizes[0];

    int n4 = n >> 2;
    int blocks = NBLOCKS;
    int maxBlocks = (n4 + NTHREADS - 1) / NTHREADS;
    if (maxBlocks < 1) maxBlocks = 1;
    if (blocks > maxBlocks) blocks = maxBlocks;

    bspline_actf_kernel<<<blocks, NTHREADS>>>(x, grid, W, out, n);
}

// round 7
// speedup vs baseline: 1.0388x; 1.0013x over previous
#include <cuda_runtime.h>
#include <cuda_fp16.h>

// BSplineACTF: per-channel cubic B-spline activation, uniform knots.
// x:[16,256,256,32] f32, grid:[12] f32, W:[32,8] f32 -> out f32.
//
// R7: half-interval coefficient table (26 slots/channel). Each half-slot holds
// the interval cubic re-centered at the half-slot midpoint: q(d) = p(a + d/2),
// d in [-0.5, 0.5). The hot loop needs NO interval/parity reconstruction:
//   us = fma(x, 2/h, bias); clamp; magic-add floor; d = us - rounded;
//   LDS.64 coeffs (fp16x4); 3x FMA Horner.
// Rows 0,1,24,25 are zero (out-of-range x -> 0 via clamp). 14 instrs/element.

#define NTHREADS 256
#define NBLOCKS  2368

#define MAGIC_F   12582912.0f       // 1.5 * 2^23, ULP = 1.0 in its binade
#define MAGIC_I   0x4B400000        // __float_as_int(12582912.0f)

__global__ __launch_bounds__(NTHREADS) void bspline_actf_kernel(
    const float* __restrict__ x,
    const float* __restrict__ grid,
    const float* __restrict__ W,
    float* __restrict__ out,
    int n)
{
    // [channel][half-slot] packed re-centered cubic: lo=(q0,q1), hi=(q2,q3) fp16.
    __shared__ uint2 sc[32 * 26];

    const float g0     = grid[0];
    const float g11    = grid[11];
    const float h      = (g11 - g0) * (1.0f / 11.0f);
    const float inv2h  = 2.0f / h;
    // w = (x-g0)*inv2h + 2 ; us = w - 0.5
    const float bias   = -g0 * inv2h + 1.5f;

    // ---- one-time per-block coefficient build (832 records) ----
    for (int idx = threadIdx.x; idx < 32 * 26; idx += NTHREADS) {
        int c = idx / 26;
        int s = idx - c * 26;
        uint2 rec = make_uint2(0u, 0u);
        if (s >= 2 && s <= 23) {
            int j = (s - 2) >> 1;        // interval 0..10
            int b = (s - 2) & 1;         // half within interval
            const float* Wc = W + c * 8;
            float w0 = (j     >= 0 && j     < 8) ? __ldg(Wc + j)     : 0.0f;
            float w1 = (j - 1 >= 0 && j - 1 < 8) ? __ldg(Wc + j - 1) : 0.0f;
            float w2 = (j - 2 >= 0 && j - 2 < 8) ? __ldg(Wc + j - 2) : 0.0f;
            float w3 = (j - 3 >= 0 && j - 3 < 8) ? __ldg(Wc + j - 3) : 0.0f;
            // interval cubic p(t) = c0 + c1 t + c2 t^2 + c3 t^3, t in [0,1)
            float c0 = (w1 + 4.0f * w2 + w3) * (1.0f / 6.0f);
            float c1 = (w1 - w3) * 0.5f;
            float c2 = (w1 - 2.0f * w2 + w3) * 0.5f;
            float c3 = (w0 - 3.0f * w1 + 3.0f * w2 - w3) * (1.0f / 6.0f);
            // re-center: q(d) = p(a + d/2), a = b/2 + 1/4, d in [-0.5, 0.5)
            float a  = 0.5f * b + 0.25f;
            float q0 = ((c3 * a + c2) * a + c1) * a + c0;
            float q1 = 0.5f   * ((3.0f * c3 * a + 2.0f * c2) * a + c1);
            float q2 = 0.25f  * (3.0f * c3 * a + c2);
            float q3 = 0.125f * c3;
            __half2 lo = __floats2half2_rn(q0, q1);
            __half2 hi = __floats2half2_rn(q2, q3);
            rec.x = *reinterpret_cast<unsigned int*>(&lo);
            rec.y = *reinterpret_cast<unsigned int*>(&hi);
        }
        sc[idx] = rec;
    }
    __syncthreads();

    const int gtid   = blockIdx.x * NTHREADS + threadIdx.x;
    const int stride = gridDim.x * NTHREADS;   // in float4 vectors; % 8 == 0
    const int n4     = n >> 2;

    // channel quartet of this thread's vectors is loop-invariant
    const int c0i = (gtid & 7) * 4;
    const uint2* __restrict__ row0 = sc + (c0i + 0) * 26;
    const uint2* __restrict__ row1 = sc + (c0i + 1) * 26;
    const uint2* __restrict__ row2 = sc + (c0i + 2) * 26;
    const uint2* __restrict__ row3 = sc + (c0i + 3) * 26;

    const float4* __restrict__ x4 = (const float4*)x;
    float4* __restrict__ o4       = (float4*)out;

    auto evalspline = [&](float xv, const uint2* __restrict__ rowp) -> float {
        float us = fmaf(xv, inv2h, bias);
        us = fminf(fmaxf(us, -0.49f), 25.49f);   // slots 0 / 25 are zero rows
        float f   = us + MAGIC_F;                // RNE(us), exact in binade
        int  idx2 = __float_as_int(f) - MAGIC_I; // slot 0..25
        float d   = us - (f - MAGIC_F);          // d in [-0.5, 0.5]
        uint2 rec = rowp[idx2];                  // LDS.64
        __half2 lo = *reinterpret_cast<__half2*>(&rec.x);
        __half2 hi = *reinterpret_cast<__half2*>(&rec.y);
        float2 f01 = __half22float2(lo);
        float2 f23 = __half22float2(hi);
        return fmaf(fmaf(fmaf(f23.y, d, f23.x), d, f01.y), d, f01.x);
    };

    auto eval_vec = [&](float4 xv) -> float4 {
        float4 ov;
        ov.x = evalspline(xv.x, row0);
        ov.y = evalspline(xv.y, row1);
        ov.z = evalspline(xv.z, row2);
        ov.w = evalspline(xv.w, row3);
        return ov;
    };

    // 2-way unrolled grid-stride loop (best measured schedule)
    int v = gtid;
    for (; v + stride < n4; v += 2 * stride) {
        float4 xa = x4[v];
        float4 xb = x4[v + stride];
        float4 oa = eval_vec(xa);
        float4 ob = eval_vec(xb);
        o4[v]          = oa;
        o4[v + stride] = ob;
    }
    if (v < n4) {
        o4[v] = eval_vec(x4[v]);
    }

    // scalar tail (n % 4) — not hit for this shape, kept for safety
    for (int e = (n4 << 2) + gtid; e < n; e += stride) {
        int c = e & 31;
        out[e] = evalspline(x[e], sc + c * 26);
    }
}

extern "C" void kernel_launch(void* const* d_in, const int* in_sizes, int n_in,
                              void* d_out, int out_size)
{
    const float* x    = (const float*)d_in[0];
    const float* grid = (const float*)d_in[1];
    const float* W    = (const float*)d_in[2];
    float* out        = (float*)d_out;
    int n = in_sizes[0];

    int n4 = n >> 2;
    int blocks = NBLOCKS;
    int maxBlocks = (n4 + NTHREADS - 1) / NTHREADS;
    if (maxBlocks < 1) maxBlocks = 1;
    if (blocks > maxBlocks) blocks = maxBlocks;

    bspline_actf_kernel<<<blocks, NTHREADS>>>(x, grid, W, out, n);
}